// round 3
// baseline (speedup 1.0000x reference)
#include <cuda_runtime.h>
#include <cstdint>

#define B_DIM    256
#define T_DIM    168
#define C_DIM    1024
#define NSEQ     168
#define HORIZON  24
#define T_STAGE  24
#define GROUPS   7                       // 168 / 24

#define WPB          4                   // warps per block
#define NUM_BLOCKS   592                 // 148 SMs x 4 blocks
#define FIRST_DYN    (NUM_BLOCKS * WPB)  // 2368 static first tiles
#define NUM_TILES    4096                // 256 b x 16 channel-groups of 64

#define STAGE_U64    (T_STAGE * 32)      // 768 u64 = 6144 B per stage
#define WARP_U64     (2 * STAGE_U64)     // double buffer per warp
#define WOFF_U64     (WPB * WARP_U64)    // w table after 4 warp buffers
#define SMEM_BYTES   ((WOFF_U64 + NSEQ) * 8)   // 49152 + 1344 = 50496

__device__ int g_ctr;

__global__ void reset_ctr_kernel() { g_ctr = FIRST_DYN; }

// ---- packed f32x2 helpers ----
__device__ __forceinline__ unsigned long long pack2(float lo, float hi) {
    unsigned long long r;
    asm("mov.b64 %0, {%1, %2};" : "=l"(r) : "f"(lo), "f"(hi));
    return r;
}
__device__ __forceinline__ unsigned long long fma2(unsigned long long a,
                                                   unsigned long long b,
                                                   unsigned long long c) {
    unsigned long long d;
    asm("fma.rn.f32x2 %0, %1, %2, %3;" : "=l"(d) : "l"(a), "l"(b), "l"(c));
    return d;
}
__device__ __forceinline__ unsigned long long add2(unsigned long long a,
                                                   unsigned long long b) {
    unsigned long long d;
    asm("add.rn.f32x2 %0, %1, %2;" : "=l"(d) : "l"(a), "l"(b));
    return d;
}
__device__ __forceinline__ void cp16(uint32_t saddr, const void* gptr) {
    asm volatile("cp.async.cg.shared.global [%0], [%1], 16;"
                 :: "r"(saddr), "l"(gptr));
}
__device__ __forceinline__ void cp_commit() {
    asm volatile("cp.async.commit_group;");
}
template<int N>
__device__ __forceinline__ void cp_wait() {
    asm volatile("cp.async.wait_group %0;" :: "n"(N));
}

__global__ __launch_bounds__(128, 4)
void ar_forecast_kernel(const float* __restrict__ y,
                        const float* __restrict__ w,
                        const float* __restrict__ bias,
                        float* __restrict__ out) {
    extern __shared__ unsigned long long sm[];
    const int tid  = threadIdx.x;
    const int wid  = tid >> 5;
    const int lane = tid & 31;

    // w duplicated-pair table (block-shared, loaded once)
    for (int i = tid; i < NSEQ; i += 128) {
        float wv = w[i];
        sm[WOFF_U64 + i] = pack2(wv, wv);
    }
    __syncthreads();                     // the ONLY block barrier

    unsigned long long* wbuf = sm + wid * WARP_U64;
    const uint32_t sbase =
        (uint32_t)__cvta_generic_to_shared((void*)wbuf);

    // prefetch one 24-row group of this tile into buffer `buf`
    // rows are 256 B wide (64 channels); 12 x 16B chunks per lane
    auto prefetch = [&](const char* tilebase, int g, int buf) {
        const uint32_t sdst = sbase + buf * (STAGE_U64 * 8);
        const char*    gsrc = tilebase + (long long)g * T_STAGE * 4096;
#pragma unroll
        for (int j = 0; j < 12; ++j) {
            int id  = j * 32 + lane;
            int row = id >> 4;               // 0..23
            int col = (id & 15) << 4;        // 0..240 bytes
            cp16(sdst + row * 256 + col, gsrc + (long long)row * 4096 + col);
        }
        cp_commit();
    };

    const float bvf = bias[0];
    const unsigned long long b2 = pack2(bvf, bvf);

    unsigned long long acc[HORIZON];
    float* prev_op = nullptr;

    int tile = blockIdx.x * WPB + wid;   // static first tile

    while (tile < NUM_TILES) {
        const int b  = tile >> 4;
        const int c0 = (tile & 15) * 64;
        const char* tilebase =
            (const char*)(y + ((long long)b * T_DIM) * C_DIM + c0);
        float* op = out + ((long long)b * HORIZON) * C_DIM + c0 + lane * 2;

        // fill the pipe for this tile
        prefetch(tilebase, 0, 0);
        prefetch(tilebase, 1, 1);

        // grab next tile now; result needed a whole tile later
        int next_tile;
        if (lane == 0) next_tile = atomicAdd(&g_ctr, 1);
        next_tile = __shfl_sync(0xffffffffu, next_tile, 0);

        // ---- deferred epilogue of PREVIOUS tile (overlaps the fill) ----
        if (prev_op) {
            unsigned long long pred[HORIZON];
#pragma unroll
            for (int h = 0; h < HORIZON; ++h) {
                unsigned long long p = add2(acc[h], b2);
#pragma unroll
                for (int j = 0; j < h; ++j)
                    p = fma2(sm[WOFF_U64 + (NSEQ - h + j)], pred[j], p);
                pred[h] = p;
            }
#pragma unroll
            for (int h = 0; h < HORIZON; ++h)
                *reinterpret_cast<unsigned long long*>(
                    prev_op + (long long)h * C_DIM) = pred[h];
        }

#pragma unroll
        for (int h = 0; h < HORIZON; ++h) acc[h] = 0ull;

        // ---- group 0: triangular prologue ----
        cp_wait<1>();
        __syncwarp();
        {
            const unsigned long long* st = wbuf;       // buffer 0
#pragma unroll
            for (int t = 0; t < T_STAGE; ++t) {
                unsigned long long y2 = st[t * 32 + lane];
#pragma unroll
                for (int h = 0; h <= t; ++h)
                    acc[h] = fma2(y2, sm[WOFF_U64 + (t - h)], acc[h]);
            }
        }
        prefetch(tilebase, 2, 0);                      // refill buffer 0

        unsigned long long wreg[HORIZON];
#pragma unroll
        for (int i = 0; i < HORIZON; ++i) wreg[i] = sm[WOFF_U64 + i];

        // ---- groups 1..6 ----
#pragma unroll 1
        for (int g = 1; g < GROUPS; ++g) {
            if (g < GROUPS - 1) { cp_wait<1>(); } else { cp_wait<0>(); }
            __syncwarp();

            const unsigned long long* st = wbuf + (g & 1) * STAGE_U64;
            const int tb = g * T_STAGE;
#pragma unroll
            for (int k = 0; k < T_STAGE; ++k) {
                wreg[k] = sm[WOFF_U64 + tb + k];       // slot (tb+k)%24 == k
                unsigned long long y2 = st[k * 32 + lane];
#pragma unroll
                for (int h = 0; h < HORIZON; ++h) {
                    const int slot = ((k - h) % HORIZON + HORIZON) % HORIZON;
                    acc[h] = fma2(y2, wreg[slot], acc[h]);
                }
            }
            if (g + 2 < GROUPS) prefetch(tilebase, g + 2, g & 1);
        }

        prev_op = op;
        tile = next_tile;
    }

    // ---- final deferred epilogue ----
    if (prev_op) {
        unsigned long long pred[HORIZON];
#pragma unroll
        for (int h = 0; h < HORIZON; ++h) {
            unsigned long long p = add2(acc[h], b2);
#pragma unroll
            for (int j = 0; j < h; ++j)
                p = fma2(sm[WOFF_U64 + (NSEQ - h + j)], pred[j], p);
            pred[h] = p;
        }
#pragma unroll
        for (int h = 0; h < HORIZON; ++h)
            *reinterpret_cast<unsigned long long*>(
                prev_op + (long long)h * C_DIM) = pred[h];
    }
}

extern "C" void kernel_launch(void* const* d_in, const int* in_sizes, int n_in,
                              void* d_out, int out_size) {
    // metadata order: x (unused), y, w, b
    const float* y    = (const float*)d_in[1];
    const float* w    = (const float*)d_in[2];
    const float* bias = (const float*)d_in[3];
    float* out        = (float*)d_out;

    static bool attr_set = false;
    if (!attr_set) {
        cudaFuncSetAttribute(ar_forecast_kernel,
                             cudaFuncAttributeMaxDynamicSharedMemorySize,
                             SMEM_BYTES);
        attr_set = true;
    }

    reset_ctr_kernel<<<1, 1>>>();
    ar_forecast_kernel<<<NUM_BLOCKS, 128, SMEM_BYTES>>>(y, w, bias, out);
}

// round 4
// speedup vs baseline: 1.3051x; 1.3051x over previous
#include <cuda_runtime.h>
#include <cstdint>

#define B_DIM    256
#define T_DIM    168
#define C_DIM    1024
#define NSEQ     168
#define HORIZON  24
#define T_STAGE  24
#define GROUPS   7                        // 168 / 24

#define STAGE_U64  (T_STAGE * 32)         // 768 u64 = 6 KB per warp-stage
#define WARP_U64   (2 * STAGE_U64)        // per-warp double buffer (12 KB)
#define WOFF_U64   (4 * WARP_U64)         // w table after 4 warp buffers
#define SMEM_BYTES ((WOFF_U64 + NSEQ) * 8)   // 49152 + 1344 = 50496

// ---- packed f32x2 helpers (Blackwell sm_103a) ----
__device__ __forceinline__ unsigned long long pack2(float lo, float hi) {
    unsigned long long r;
    asm("mov.b64 %0, {%1, %2};" : "=l"(r) : "f"(lo), "f"(hi));
    return r;
}
__device__ __forceinline__ unsigned long long fma2(unsigned long long a,
                                                   unsigned long long b,
                                                   unsigned long long c) {
    unsigned long long d;
    asm("fma.rn.f32x2 %0, %1, %2, %3;" : "=l"(d) : "l"(a), "l"(b), "l"(c));
    return d;
}
__device__ __forceinline__ unsigned long long add2(unsigned long long a,
                                                   unsigned long long b) {
    unsigned long long d;
    asm("add.rn.f32x2 %0, %1, %2;" : "=l"(d) : "l"(a), "l"(b));
    return d;
}
__device__ __forceinline__ void cp16(uint32_t saddr, const void* gptr) {
    asm volatile("cp.async.cg.shared.global [%0], [%1], 16;"
                 :: "r"(saddr), "l"(gptr));
}
__device__ __forceinline__ void cp_commit() {
    asm volatile("cp.async.commit_group;");
}
template<int N>
__device__ __forceinline__ void cp_wait() {
    asm volatile("cp.async.wait_group %0;" :: "n"(N));
}

// Block = 128 threads = 4 warps; each warp owns 64 channels (32 pairs) of one b.
// Grid = (C/256, B) = (4, 256) -> 1024 blocks. Steady state is barrier-free:
// every warp runs its own 2-stage cp.async pipeline over its private smem slice.
__global__ __launch_bounds__(128, 4)
void ar_forecast_kernel(const float* __restrict__ y,
                        const float* __restrict__ w,
                        const float* __restrict__ bias,
                        float* __restrict__ out) {
    extern __shared__ unsigned long long sm[];
    const int tid  = threadIdx.x;
    const int wid  = tid >> 5;
    const int lane = tid & 31;

    // block-shared duplicated-pair w table (single barrier in the kernel)
    for (int i = tid; i < NSEQ; i += 128) {
        float wv = w[i];
        sm[WOFF_U64 + i] = pack2(wv, wv);
    }
    __syncthreads();

    const unsigned long long* wt = sm + WOFF_U64;
    unsigned long long* wbuf = sm + wid * WARP_U64;
    const uint32_t sbase = (uint32_t)__cvta_generic_to_shared((void*)wbuf);

    const int b  = blockIdx.y;
    const int cw = blockIdx.x * 256 + wid * 64;        // warp's first channel
    // warp's y slice: 256 B per row, row stride 4096 B
    const char* ybase = (const char*)(y + ((long long)b * T_DIM) * C_DIM + cw);

    // prefetch one 24-row group into warp-local buffer `buf` (12 cp16 / lane)
    auto prefetch = [&](int g, int buf) {
        const uint32_t sdst = sbase + buf * (STAGE_U64 * 8);
        const char*    gsrc = ybase + (long long)g * T_STAGE * 4096;
#pragma unroll
        for (int j = 0; j < 12; ++j) {
            int id  = j * 32 + lane;
            int row = id >> 4;               // 0..23
            int col = (id & 15) << 4;        // 0..240 bytes
            cp16(sdst + row * 256 + col, gsrc + (long long)row * 4096 + col);
        }
        cp_commit();
    };

    prefetch(0, 0);
    prefetch(1, 1);

    unsigned long long acc[HORIZON];
#pragma unroll
    for (int h = 0; h < HORIZON; ++h) acc[h] = 0ull;

    // ---- group 0: triangular prologue ----
    cp_wait<1>();
    __syncwarp();
    {
        const unsigned long long* st = wbuf;           // buffer 0
#pragma unroll
        for (int t = 0; t < T_STAGE; ++t) {
            unsigned long long y2 = st[t * 32 + lane];
#pragma unroll
            for (int h = 0; h <= t; ++h)
                acc[h] = fma2(y2, wt[t - h], acc[h]);
        }
    }
    prefetch(2, 0);                                    // refill buffer 0

    unsigned long long wreg[HORIZON];
#pragma unroll
    for (int i = 0; i < HORIZON; ++i) wreg[i] = wt[i];

    // ---- groups 1..6: uniform 24-wide windows, warp-local pipeline ----
#pragma unroll 1
    for (int g = 1; g < GROUPS; ++g) {
        if (g < GROUPS - 1) { cp_wait<1>(); } else { cp_wait<0>(); }
        __syncwarp();

        const unsigned long long* st = wbuf + (g & 1) * STAGE_U64;
        const int tb = g * T_STAGE;
#pragma unroll
        for (int k = 0; k < T_STAGE; ++k) {
            wreg[k] = wt[tb + k];                      // slot (tb+k)%24 == k
            unsigned long long y2 = st[k * 32 + lane];
#pragma unroll
            for (int h = 0; h < HORIZON; ++h) {
                const int slot = ((k - h) % HORIZON + HORIZON) % HORIZON;
                acc[h] = fma2(y2, wreg[slot], acc[h]);
            }
        }
        if (g + 2 < GROUPS) prefetch(g + 2, g & 1);
    }

    // ---- AR recursion over the 24 predictions (inline, acc dies into pred) ----
    const float bvf = bias[0];
    const unsigned long long b2 = pack2(bvf, bvf);

    unsigned long long pred[HORIZON];
#pragma unroll
    for (int h = 0; h < HORIZON; ++h) {
        unsigned long long p = add2(acc[h], b2);
#pragma unroll
        for (int j = 0; j < h; ++j)
            p = fma2(wt[NSEQ - h + j], pred[j], p);
        pred[h] = p;
    }

    // ---- store out[b, h, c] ----
    float* op = out + ((long long)b * HORIZON) * C_DIM + cw + lane * 2;
#pragma unroll
    for (int h = 0; h < HORIZON; ++h)
        *reinterpret_cast<unsigned long long*>(op + (long long)h * C_DIM) = pred[h];
}

extern "C" void kernel_launch(void* const* d_in, const int* in_sizes, int n_in,
                              void* d_out, int out_size) {
    // metadata order: x (unused), y, w, b
    const float* y    = (const float*)d_in[1];
    const float* w    = (const float*)d_in[2];
    const float* bias = (const float*)d_in[3];
    float* out        = (float*)d_out;

    static bool attr_set = false;
    if (!attr_set) {
        cudaFuncSetAttribute(ar_forecast_kernel,
                             cudaFuncAttributeMaxDynamicSharedMemorySize,
                             SMEM_BYTES);
        attr_set = true;
    }

    dim3 grid(C_DIM / 256, B_DIM);
    ar_forecast_kernel<<<grid, 128, SMEM_BYTES>>>(y, w, bias, out);
}